// round 8
// baseline (speedup 1.0000x reference)
#include <cuda_runtime.h>
#include <cstdint>

#define N_NODES 16384
#define A_ANCH  256
#define D_LAT   32

// B fragments for mma.m16n8k8.tf32, precomputed in fragment order and pre-split:
//   g_Bfrag[((ks*4 + nt)*32 + lane)] = (b0_hi, b1_hi, b0_lo, b1_lo)
// where b0 = Mscaled[ks*8 + lane%4][nt*8 + lane/4], b1 = same with k-row +4.
// Mscaled = (1/256) * (anchor_emb @ W1), split into tf32 hi + tf32 lo.
__device__ float4 g_Bfrag[32 * 4 * 32];   // 64 KB
__device__ float  g_c[D_LAT];             // c = b + (1/256)*colsum(embeds[:256]) @ W2

// ---------------------------------------------------------------------------
// Kernel 1: precompute B fragments + c. Grid = 9 blocks x 256 threads.
//   blocks 0..7: M rows 32b..32b+31 -> fragments for ksteps 4b..4b+3
//   block 8:     c
// ---------------------------------------------------------------------------
__global__ __launch_bounds__(256) void precompute_kernel(
    const float* __restrict__ embeds,
    const float* __restrict__ W,       // [64,32]: W1 rows 0..31, W2 rows 32..63
    const float* __restrict__ b,       // [32]
    const int*   __restrict__ anchor_ids)
{
    __shared__ float Wsh[D_LAT * D_LAT];
    __shared__ float esh[32][32];
    __shared__ float Ms[32][33];       // padded
    __shared__ float ssh[D_LAT];

    const int t   = threadIdx.x;
    const int blk = blockIdx.x;
    const int j   = t & 31;

    if (blk < 8) {
        #pragma unroll
        for (int i = t; i < D_LAT * D_LAT; i += 256) Wsh[i] = W[i];
        for (int r = t >> 5; r < 32; r += 8) {
            int id = anchor_ids[blk * 32 + r];
            esh[r][j] = embeds[id * D_LAT + j];
        }
        __syncthreads();
        for (int r = t >> 5; r < 32; r += 8) {
            float acc = 0.f;
            #pragma unroll
            for (int d = 0; d < D_LAT; d++) acc += esh[r][d] * Wsh[d * D_LAT + j];
            Ms[r][j] = acc * (1.0f / 256.0f);
        }
        __syncthreads();
        // build fragments: this block covers global ksteps 4*blk .. 4*blk+3
        #pragma unroll
        for (int i = 0; i < 2; i++) {
            int idx  = t + 256 * i;          // 0..511
            int lane = idx & 31;
            int nt   = (idx >> 5) & 3;
            int kl   = (idx >> 7) & 3;
            int krow = kl * 8 + (lane & 3);
            int col  = nt * 8 + (lane >> 2);
            float b0 = Ms[krow][col];
            float b1 = Ms[krow + 4][col];
            unsigned h0, h1, l0, l1;
            asm("cvt.rna.tf32.f32 %0, %1;" : "=r"(h0) : "f"(b0));
            asm("cvt.rna.tf32.f32 %0, %1;" : "=r"(h1) : "f"(b1));
            float r0 = b0 - __uint_as_float(h0);
            float r1 = b1 - __uint_as_float(h1);
            asm("cvt.rna.tf32.f32 %0, %1;" : "=r"(l0) : "f"(r0));
            asm("cvt.rna.tf32.f32 %0, %1;" : "=r"(l1) : "f"(r1));
            int ks = blk * 4 + kl;
            g_Bfrag[(ks * 4 + nt) * 32 + lane] =
                make_float4(__uint_as_float(h0), __uint_as_float(h1),
                            __uint_as_float(l0), __uint_as_float(l1));
        }
    } else {
        #pragma unroll
        for (int i = t; i < D_LAT * D_LAT; i += 256) Wsh[i] = W[D_LAT * D_LAT + i];
        if (t < D_LAT) ssh[t] = 0.f;
        __syncthreads();
        {
            int grp = t >> 5;
            float part = 0.f;
            #pragma unroll 4
            for (int i = 0; i < 32; i++)
                part += embeds[(grp * 32 + i) * D_LAT + j];
            atomicAdd(&ssh[j], part);
        }
        __syncthreads();
        if (t < D_LAT) {
            float acc = 0.f;
            #pragma unroll
            for (int d = 0; d < D_LAT; d++) acc += ssh[d] * Wsh[d * D_LAT + t];
            g_c[t] = b[t] + acc * (1.0f / 256.0f);
        }
    }
}

// ---------------------------------------------------------------------------
// Kernel 2: tensor-core GEMM  out = dists^T @ M + c  via mma.m16n8k8.tf32.
// Grid = 256 CTAs x 128 threads (4 warps). Warp w: rows blk*64 + w*16 .. +15.
// K = 256 -> 32 ksteps. Per kstep per warp: 4 scalar LDG.32 (A, from dists),
// 4 LDG.128 (B frags, L1/L2-resident), 12 MMA (3-pass split). No smem.
// ---------------------------------------------------------------------------
#define MMA(AC, A0, A1, A2, A3, B0, B1)                                       \
    asm("mma.sync.aligned.m16n8k8.row.col.f32.tf32.tf32.f32 "                 \
        "{%0,%1,%2,%3},{%4,%5,%6,%7},{%8,%9},{%0,%1,%2,%3};"                  \
        : "+f"(AC[0]), "+f"(AC[1]), "+f"(AC[2]), "+f"(AC[3])                  \
        : "r"(A0), "r"(A1), "r"(A2), "r"(A3), "r"(B0), "r"(B1));

__global__ __launch_bounds__(128) void pnn_mma_kernel(
    const float* __restrict__ dists,   // [A, N]
    float*       __restrict__ out)     // [N, 32]
{
    const int t    = threadIdx.x;
    const int lane = t & 31;
    const int w    = t >> 5;
    const int n0   = blockIdx.x * 64 + w * 16;

    const int rowA = n0 + (lane >> 2);
    const int colA = lane & 3;
    const float* pa = dists + (size_t)colA * N_NODES + rowA;
    const size_t N4 = 4 * (size_t)N_NODES;

    // ---- A prefetch depth 4 (independent of precompute; runs under PDL) ----
    float fa[4][4];
    #pragma unroll
    for (int p = 0; p < 4; p++) {
        size_t o = (size_t)(p * 8) * N_NODES;
        fa[p][0] = pa[o];
        fa[p][1] = pa[o + 8];
        fa[p][2] = pa[o + N4];
        fa[p][3] = pa[o + N4 + 8];
    }

    cudaGridDependencySynchronize();

    const float4* pb = g_Bfrag + lane;
    float4 fbA[4], fbB[4];
    #pragma unroll
    for (int nt = 0; nt < 4; nt++) {
        fbA[nt] = pb[(0 * 4 + nt) << 5];
        fbB[nt] = pb[(1 * 4 + nt) << 5];
    }

    float acc[4][4];
    #pragma unroll
    for (int i = 0; i < 4; i++)
        #pragma unroll
        for (int k = 0; k < 4; k++) acc[i][k] = 0.f;

    #define STEP(u, FB) {                                                         \
        const int ks = it + (u);                                                  \
        unsigned ah[4], al[4];                                                    \
        _Pragma("unroll")                                                         \
        for (int i = 0; i < 4; i++) {                                             \
            float av = fa[u][i];                                                  \
            asm("cvt.rna.tf32.f32 %0, %1;" : "=r"(ah[i]) : "f"(av));              \
            float lo = av - __uint_as_float(ah[i]);                               \
            asm("cvt.rna.tf32.f32 %0, %1;" : "=r"(al[i]) : "f"(lo));              \
        }                                                                         \
        {                                                                         \
            size_t o = (size_t)((((ks) + 4) & 31) * 8) * N_NODES;                 \
            fa[u][0] = pa[o];                                                     \
            fa[u][1] = pa[o + 8];                                                 \
            fa[u][2] = pa[o + N4];                                                \
            fa[u][3] = pa[o + N4 + 8];                                            \
        }                                                                         \
        _Pragma("unroll")                                                         \
        for (int nt = 0; nt < 4; nt++) {                                          \
            unsigned b0h = __float_as_uint(FB[nt].x);                             \
            unsigned b1h = __float_as_uint(FB[nt].y);                             \
            unsigned b0l = __float_as_uint(FB[nt].z);                             \
            unsigned b1l = __float_as_uint(FB[nt].w);                             \
            MMA(acc[nt], ah[0], ah[1], ah[2], ah[3], b0h, b1h);                   \
            MMA(acc[nt], ah[0], ah[1], ah[2], ah[3], b0l, b1l);                   \
            MMA(acc[nt], al[0], al[1], al[2], al[3], b0h, b1h);                   \
        }                                                                         \
        _Pragma("unroll")                                                         \
        for (int nt = 0; nt < 4; nt++)                                            \
            FB[nt] = pb[(((((ks) + 2) & 31) * 4 + nt) << 5)];                     \
    }

    for (int it = 0; it < 32; it += 4) {
        STEP(0, fbA)
        STEP(1, fbB)
        STEP(2, fbA)
        STEP(3, fbB)
    }
    #undef STEP

    // ---- epilogue: add c, write float2 pairs ----
    const int r0  = n0 + (lane >> 2);
    #pragma unroll
    for (int nt = 0; nt < 4; nt++) {
        int col = nt * 8 + 2 * (lane & 3);
        float2 cc = *(const float2*)(g_c + col);
        float2 v0 = make_float2(acc[nt][0] + cc.x, acc[nt][1] + cc.y);
        float2 v1 = make_float2(acc[nt][2] + cc.x, acc[nt][3] + cc.y);
        *(float2*)(out + (size_t)r0 * D_LAT + col)       = v0;
        *(float2*)(out + (size_t)(r0 + 8) * D_LAT + col) = v1;
    }
}

extern "C" void kernel_launch(void* const* d_in, const int* in_sizes, int n_in,
                              void* d_out, int out_size)
{
    const float* embeds     = (const float*)d_in[0];
    const float* dists      = (const float*)d_in[1];
    const float* W_hidden   = (const float*)d_in[2];
    const float* b_hidden   = (const float*)d_in[3];
    const int*   anchor_ids = (const int*)  d_in[4];
    float*       out        = (float*)d_out;

    precompute_kernel<<<9, 256>>>(embeds, W_hidden, b_hidden, anchor_ids);

    cudaLaunchConfig_t cfg = {};
    cfg.gridDim  = dim3(N_NODES / 64, 1, 1);
    cfg.blockDim = dim3(128, 1, 1);
    cfg.dynamicSmemBytes = 0;
    cfg.stream = 0;
    cudaLaunchAttribute attr[1];
    attr[0].id = cudaLaunchAttributeProgrammaticStreamSerialization;
    attr[0].val.programmaticStreamSerializationAllowed = 1;
    cfg.attrs = attr;
    cfg.numAttrs = 1;

    cudaError_t e = cudaLaunchKernelEx(&cfg, pnn_mma_kernel, dists, out);
    if (e != cudaSuccess) {
        pnn_mma_kernel<<<N_NODES / 64, 128>>>(dists, out);
    }
}